// round 10
// baseline (speedup 1.0000x reference)
#include <cuda_runtime.h>
#include <stdint.h>

#define P1 2654435761u
#define P2 805459861u

// Table gather with 128B L2 prefetch: within a blocked pass every sibling
// sector of the fetched line is guaranteed-useful (all rows requested ~3.8x),
// so full-line fills amortize DRAM sectors 4:1.
__device__ __forceinline__ float4 ldg_tab128(const float4* p) {
    float4 v;
    asm volatile("ld.global.nc.L2::128B.v4.f32 {%0,%1,%2,%3}, [%4];"
                 : "=f"(v.x), "=f"(v.y), "=f"(v.z), "=f"(v.w) : "l"(p));
    return v;
}
__device__ __forceinline__ float ldg_stream(const float* p) {
    float v;
    asm volatile("ld.global.cs.f32 %0, [%1];" : "=f"(v) : "l"(p));
    return v;
}
__device__ __forceinline__ void stg_stream(float4* p, float4 v) {
    asm volatile("st.global.cs.v4.f32 [%0], {%1,%2,%3,%4};"
                 :: "l"(p), "f"(v.x), "f"(v.y), "f"(v.z), "f"(v.w) : "memory");
}

// Two-pass L2 blocking (validated in R9: ~75% in-pass hit) with the R9 waste
// removed: 2 points per thread restores ~8 in-flight gathers despite half the
// corners being predicated off, and table loads prefetch full 128B lines.
// Layout per point: pair-lane (lane 2k+h = point k, 16B half h).
template <bool POW2, bool ACCUM>
__global__ __launch_bounds__(256)
void hash_interp_pass2(const float* __restrict__ pts,
                       const float* __restrict__ feat,
                       float* __restrict__ out,
                       int n, unsigned buckets, unsigned mask,
                       unsigned lo, unsigned hi)
{
    const unsigned lane = threadIdx.x & 31u;
    const int gwarp = (int)((blockIdx.x * blockDim.x + threadIdx.x) >> 5);
    const unsigned h = lane & 1u;

    const float4* fbase = reinterpret_cast<const float4*>(feat);

    // two points per thread: k and k+16 within a 32-point warp tile
    int pid[2];
    pid[0] = gwarp * 32 + (int)(lane >> 1);
    pid[1] = pid[0] + 16;

    unsigned slot[2][8];
    float w[2][8];
    bool pvalid[2];

#pragma unroll
    for (int j = 0; j < 2; j++) {
        const bool valid = (pid[j] < n);
        pvalid[j] = valid;
        const int p = valid ? pid[j] : 0;

        const float px = ldg_stream(pts + 3 * (size_t)p + 0);
        const float py = ldg_stream(pts + 3 * (size_t)p + 1);
        const float pz = ldg_stream(pts + 3 * (size_t)p + 2);

        const float qx = px / 0.005f;
        const float qy = py / 0.005f;
        const float qz = pz / 0.005f;

        const float bxf = floorf(qx);
        const float byf = floorf(qy);
        const float bzf = floorf(qz);
        const int bx = (int)bxf, by = (int)byf, bz = (int)bzf;

        const float fx = qx - bxf;
        const float fy = qy - byf;
        const float fz = qz - bzf;

        const unsigned hx0 = (unsigned)bx;
        const unsigned hx1 = (unsigned)(bx + 1);
        const unsigned hy0 = (unsigned)by * P1;
        const unsigned hy1 = hy0 + P1;
        const unsigned hz0 = (unsigned)bz * P2;
        const unsigned hz1 = hz0 + P2;

        const unsigned s0 = hx0 ^ hy0 ^ hz0;
        const unsigned s1 = hx1 ^ hy0 ^ hz0;
        const unsigned s2 = hx0 ^ hy1 ^ hz0;
        const unsigned s3 = hx1 ^ hy1 ^ hz0;
        const unsigned s4 = hx0 ^ hy0 ^ hz1;
        const unsigned s5 = hx1 ^ hy0 ^ hz1;
        const unsigned s6 = hx0 ^ hy1 ^ hz1;
        const unsigned s7 = hx1 ^ hy1 ^ hz1;
        if (POW2) {
            slot[j][0] = s0 & mask; slot[j][1] = s1 & mask;
            slot[j][2] = s2 & mask; slot[j][3] = s3 & mask;
            slot[j][4] = s4 & mask; slot[j][5] = s5 & mask;
            slot[j][6] = s6 & mask; slot[j][7] = s7 & mask;
        } else {
            slot[j][0] = s0 % buckets; slot[j][1] = s1 % buckets;
            slot[j][2] = s2 % buckets; slot[j][3] = s3 % buckets;
            slot[j][4] = s4 % buckets; slot[j][5] = s5 % buckets;
            slot[j][6] = s6 % buckets; slot[j][7] = s7 % buckets;
        }

        const float wx0 = 1.0f - fx, wx1 = fx;
        const float wy0 = 1.0f - fy, wy1 = fy;
        const float wz0 = 1.0f - fz, wz1 = fz;
        w[j][0] = wx0 * wy0 * wz0;
        w[j][1] = wx1 * wy0 * wz0;
        w[j][2] = wx0 * wy1 * wz0;
        w[j][3] = wx1 * wy1 * wz0;
        w[j][4] = wx0 * wy0 * wz1;
        w[j][5] = wx1 * wy0 * wz1;
        w[j][6] = wx0 * wy1 * wz1;
        w[j][7] = wx1 * wy1 * wz1;
    }

    // issue all (up to 16, avg 8 live) gathers before any consumption
    float4 v[2][8];
#pragma unroll
    for (int j = 0; j < 2; j++) {
#pragma unroll
        for (int c = 0; c < 8; c++) {
            const bool mine = (slot[j][c] >= lo) & (slot[j][c] < hi);
            float4 vv = make_float4(0.f, 0.f, 0.f, 0.f);
            if (mine) vv = ldg_tab128(fbase + ((size_t)slot[j][c] * 2 + h));
            v[j][c] = vv;
        }
    }

#pragma unroll
    for (int j = 0; j < 2; j++) {
        float a0 = 0.f, a1 = 0.f, a2 = 0.f, a3 = 0.f;
#pragma unroll
        for (int c = 0; c < 8; c++) {
            const float wc = w[j][c];
            a0 = fmaf(wc, v[j][c].x, a0);
            a1 = fmaf(wc, v[j][c].y, a1);
            a2 = fmaf(wc, v[j][c].z, a2);
            a3 = fmaf(wc, v[j][c].w, a3);
        }
        if (pvalid[j]) {
            float4* op = reinterpret_cast<float4*>(out) + ((size_t)pid[j] * 2 + h);
            if (ACCUM) {
                const float4 prev = *reinterpret_cast<const float4*>(op);
                a0 += prev.x; a1 += prev.y; a2 += prev.z; a3 += prev.w;
            }
            stg_stream(op, make_float4(a0, a1, a2, a3));
        }
    }
}

extern "C" void kernel_launch(void* const* d_in, const int* in_sizes, int n_in,
                              void* d_out, int out_size)
{
    const float* pts  = (const float*)d_in[0];
    const float* feat = (const float*)d_in[1];
    float* out = (float*)d_out;

    int n = in_sizes[0] / 3;
    unsigned buckets = (unsigned)(in_sizes[1] / 8);
    unsigned mask = buckets - 1u;
    bool pow2 = (buckets & (buckets - 1u)) == 0u;

    unsigned half = buckets / 2u;

    // 2 lanes/point, 2 points/thread -> 32 points per warp
    long long warps = ((long long)n + 31) / 32;
    long long threads_total = warps * 32;
    int threads = 256;
    int blocks = (int)((threads_total + threads - 1) / threads);

    if (pow2) {
        hash_interp_pass2<true, false><<<blocks, threads>>>(pts, feat, out, n, buckets, mask, 0u, half);
        hash_interp_pass2<true, true ><<<blocks, threads>>>(pts, feat, out, n, buckets, mask, half, buckets);
    } else {
        hash_interp_pass2<false, false><<<blocks, threads>>>(pts, feat, out, n, buckets, mask, 0u, half);
        hash_interp_pass2<false, true ><<<blocks, threads>>>(pts, feat, out, n, buckets, mask, half, buckets);
    }
}

// round 11
// speedup vs baseline: 1.7445x; 1.7445x over previous
#include <cuda_runtime.h>
#include <stdint.h>

#define P1 2654435761u
#define P2 805459861u

// Table gather with 128B line-granular L2 fill. Each table line's 4 slots are
// requested ~4x per launch, so sibling sectors are guaranteed-useful; full-line
// fills raise effective L2 table residency from ~43MB (sector fills) to ~full
// capacity, flipping the ~80% miss rate to ~90% hits in steady state.
__device__ __forceinline__ float4 ldg_tab128(const float4* p) {
    float4 v;
    asm volatile("ld.global.nc.L2::128B.v4.f32 {%0,%1,%2,%3}, [%4];"
                 : "=f"(v.x), "=f"(v.y), "=f"(v.z), "=f"(v.w) : "l"(p));
    return v;
}

// Streaming (evict-first) accessors for pts/out so they displace minimal table.
__device__ __forceinline__ float ldg_stream(const float* p) {
    float v;
    asm volatile("ld.global.cs.f32 %0, [%1];" : "=f"(v) : "l"(p));
    return v;
}
__device__ __forceinline__ void stg_stream(float4* p, float4 v) {
    asm volatile("st.global.cs.v4.f32 [%0], {%1,%2,%3,%4};"
                 :: "l"(p), "f"(v.x), "f"(v.y), "f"(v.z), "f"(v.w) : "memory");
}

// Measured-best single-pass layout (R3, 90.1us): 2 lanes per point, lane 2k+h
// handles point k, 16B half h of the 32B feature row; pair-lanes share each
// 128B line per gather -> 8 L1tex wavefronts/point, no cross-lane reduction.
template <bool POW2>
__global__ __launch_bounds__(256)
void hash_interp_half(const float* __restrict__ pts,
                      const float* __restrict__ feat,
                      float* __restrict__ out,
                      int n, unsigned buckets, unsigned mask)
{
    const unsigned lane = threadIdx.x & 31u;
    const int gwarp = (int)((blockIdx.x * blockDim.x + threadIdx.x) >> 5);

    const int p_raw = gwarp * 16 + (int)(lane >> 1);   // 16 points per warp
    const bool valid = (p_raw < n);
    const int p = valid ? p_raw : 0;
    const unsigned h = lane & 1u;                      // 16B half of the row

    // point coords (pair-lanes read identical addresses -> broadcast)
    const float px = ldg_stream(pts + 3 * (size_t)p + 0);
    const float py = ldg_stream(pts + 3 * (size_t)p + 1);
    const float pz = ldg_stream(pts + 3 * (size_t)p + 2);

    // continuous grid coords, matching reference's pts / 0.005
    const float qx = px / 0.005f;
    const float qy = py / 0.005f;
    const float qz = pz / 0.005f;

    const float bxf = floorf(qx);
    const float byf = floorf(qy);
    const float bzf = floorf(qz);
    const int bx = (int)bxf, by = (int)byf, bz = (int)bzf;

    const float fx = qx - bxf;
    const float fy = qy - byf;
    const float fz = qz - bzf;

    // per-axis hash terms
    const unsigned hx0 = (unsigned)bx;           // * 1
    const unsigned hx1 = (unsigned)(bx + 1);
    const unsigned hy0 = (unsigned)by * P1;
    const unsigned hy1 = hy0 + P1;
    const unsigned hz0 = (unsigned)bz * P2;
    const unsigned hz1 = hz0 + P2;

    unsigned slot[8];
    {
        const unsigned s0 = hx0 ^ hy0 ^ hz0;
        const unsigned s1 = hx1 ^ hy0 ^ hz0;
        const unsigned s2 = hx0 ^ hy1 ^ hz0;
        const unsigned s3 = hx1 ^ hy1 ^ hz0;
        const unsigned s4 = hx0 ^ hy0 ^ hz1;
        const unsigned s5 = hx1 ^ hy0 ^ hz1;
        const unsigned s6 = hx0 ^ hy1 ^ hz1;
        const unsigned s7 = hx1 ^ hy1 ^ hz1;
        if (POW2) {
            slot[0] = s0 & mask; slot[1] = s1 & mask; slot[2] = s2 & mask; slot[3] = s3 & mask;
            slot[4] = s4 & mask; slot[5] = s5 & mask; slot[6] = s6 & mask; slot[7] = s7 & mask;
        } else {
            slot[0] = s0 % buckets; slot[1] = s1 % buckets; slot[2] = s2 % buckets; slot[3] = s3 % buckets;
            slot[4] = s4 % buckets; slot[5] = s5 % buckets; slot[6] = s6 % buckets; slot[7] = s7 % buckets;
        }
    }

    // issue all 8 gathers up-front for MLP; pair-lanes share each 128B line
    const float4* fbase = reinterpret_cast<const float4*>(feat);
    float4 v[8];
#pragma unroll
    for (int c = 0; c < 8; c++) {
        v[c] = ldg_tab128(fbase + ((size_t)slot[c] * 2 + h));
    }

    // trilinear weights (same multiply order as reference); after the loads so
    // the ALU overlaps memory latency.
    const float wx0 = 1.0f - fx, wx1 = fx;
    const float wy0 = 1.0f - fy, wy1 = fy;
    const float wz0 = 1.0f - fz, wz1 = fz;
    float w[8];
    w[0] = wx0 * wy0 * wz0;
    w[1] = wx1 * wy0 * wz0;
    w[2] = wx0 * wy1 * wz0;
    w[3] = wx1 * wy1 * wz0;
    w[4] = wx0 * wy0 * wz1;
    w[5] = wx1 * wy0 * wz1;
    w[6] = wx0 * wy1 * wz1;
    w[7] = wx1 * wy1 * wz1;

    float a0 = 0.f, a1 = 0.f, a2 = 0.f, a3 = 0.f;
#pragma unroll
    for (int c = 0; c < 8; c++) {
        const float wc = w[c];
        a0 = fmaf(wc, v[c].x, a0);
        a1 = fmaf(wc, v[c].y, a1);
        a2 = fmaf(wc, v[c].z, a2);
        a3 = fmaf(wc, v[c].w, a3);
    }

    if (valid) {
        // lane 2k -> float4 index 2p, lane 2k+1 -> 2p+1: fully coalesced
        stg_stream(reinterpret_cast<float4*>(out) + ((size_t)p_raw * 2 + h),
                   make_float4(a0, a1, a2, a3));
    }
}

extern "C" void kernel_launch(void* const* d_in, const int* in_sizes, int n_in,
                              void* d_out, int out_size)
{
    const float* pts  = (const float*)d_in[0];
    const float* feat = (const float*)d_in[1];
    float* out = (float*)d_out;

    int n = in_sizes[0] / 3;
    unsigned buckets = (unsigned)(in_sizes[1] / 8);
    unsigned mask = buckets - 1u;
    bool pow2 = (buckets & (buckets - 1u)) == 0u;

    // 2 lanes per point -> 16 points per warp
    long long warps = ((long long)n + 15) / 16;
    long long threads_total = warps * 32;
    int threads = 256;
    int blocks = (int)((threads_total + threads - 1) / threads);

    if (pow2) {
        hash_interp_half<true><<<blocks, threads>>>(pts, feat, out, n, buckets, mask);
    } else {
        hash_interp_half<false><<<blocks, threads>>>(pts, feat, out, n, buckets, mask);
    }
}